// round 16
// baseline (speedup 1.0000x reference)
#include <cuda_runtime.h>
#include <cuda_bf16.h>
#include <cstdint>

#define BB   16
#define CIN  512
#define COUT 512
#define HH   64
#define WW   64
#define SDIM 512

#define CONV_SCALE 0.014731391274719737f   /* 1/sqrt(512*9) */
#define MOD_SCALE  0.04419417382415922f    /* 1/sqrt(512)   */
#define EPS        1e-8f

// ---------------------------------------------------------------------------
// Device scratch (allocation-free rule: __device__ globals, zero-initialized)
// ---------------------------------------------------------------------------
__device__ float g_s[BB * CIN];
__device__ float g_demod[BB * COUT];
// Padded NHWC modulated input, tf32-rounded fp32: [b][66][66][ci:512]
__device__ float g_xcat[(size_t)BB * 66 * 66 * 512];
// Weights tf32-rounded fp32: [k(9)][co(512)][ci(512)], pre-scaled
__device__ float g_wcat[(size_t)9 * COUT * CIN];

// ---------------------------------------------------------------------------
// PTX helpers (base ISA only)
// ---------------------------------------------------------------------------
__device__ __forceinline__ uint32_t smem_u32(const void* p) {
    uint32_t a;
    asm("{ .reg .u64 t; cvta.to.shared.u64 t, %1; cvt.u32.u64 %0, t; }" : "=r"(a) : "l"(p));
    return a;
}
__device__ __forceinline__ void cpa16(uint32_t dst, const void* src) {
    asm volatile("cp.async.cg.shared.global [%0], [%1], 16;" :: "r"(dst), "l"(src));
}
#define CP_COMMIT() asm volatile("cp.async.commit_group;" ::: "memory")
template <int N>
__device__ __forceinline__ void cp_wait() {
    asm volatile("cp.async.wait_group %0;" :: "n"(N) : "memory");
}
__device__ __forceinline__ void ldsm4(uint32_t* r, uint32_t addr) {
    asm volatile("ldmatrix.sync.aligned.m8n8.x4.shared.b16 {%0,%1,%2,%3}, [%4];"
                 : "=r"(r[0]), "=r"(r[1]), "=r"(r[2]), "=r"(r[3]) : "r"(addr));
}
__device__ __forceinline__ void mma1688(float* d, const uint32_t* a,
                                        uint32_t b0, uint32_t b1) {
    asm volatile(
        "mma.sync.aligned.m16n8k8.row.col.f32.tf32.tf32.f32 "
        "{%0,%1,%2,%3}, {%4,%5,%6,%7}, {%8,%9}, {%0,%1,%2,%3};"
        : "+f"(d[0]), "+f"(d[1]), "+f"(d[2]), "+f"(d[3])
        : "r"(a[0]), "r"(a[1]), "r"(a[2]), "r"(a[3]), "r"(b0), "r"(b1));
}
__device__ __forceinline__ float to_tf32(float v) {
    uint32_t r;
    asm("cvt.rna.tf32.f32 %0, %1;" : "=r"(r) : "f"(v));
    return __uint_as_float(r);
}

// ---------------------------------------------------------------------------
// Kernel 1: modulation scales
// ---------------------------------------------------------------------------
__global__ void k_style(const float* __restrict__ style,
                        const float* __restrict__ mw,
                        const float* __restrict__ mb) {
    __shared__ float st[SDIM];
    int b = blockIdx.x;
    int t = threadIdx.x;
    st[t] = style[b * SDIM + t];
    __syncthreads();
    const float4* wrow = (const float4*)(mw + (size_t)t * SDIM);
    const float4* srow = (const float4*)st;
    float acc = 0.f;
#pragma unroll 8
    for (int j = 0; j < SDIM / 4; j++) {
        float4 w4 = wrow[j];
        float4 s4 = srow[j];
        acc += w4.x * s4.x + w4.y * s4.y + w4.z * s4.z + w4.w * s4.w;
    }
    g_s[b * CIN + t] = acc * MOD_SCALE + mb[t];
}

// ---------------------------------------------------------------------------
// Kernel 2 (fused prep): blocks 0..1023 -> x-prep; 1024..1535 -> w-prep.
// Keeps total launch count at 4 so ncu's captured slot (#4) is the conv.
// ---------------------------------------------------------------------------
__global__ void k_prep(const float* __restrict__ x, const float* __restrict__ wt) {
    int id  = blockIdx.x;
    int tid = threadIdx.x;
    if (id >= 1024) {
        // ---- weight prep: co = id - 1024; ci = tid, tid+256 ----
        int co = id - 1024;
#pragma unroll
        for (int h = 0; h < 2; h++) {
            int ci = tid + h * 256;
            const float* wp = wt + ((size_t)co * CIN + ci) * 9;
#pragma unroll
            for (int k = 0; k < 9; k++)
                g_wcat[((size_t)k * COUT + co) * CIN + ci] = to_tf32(CONV_SCALE * wp[k]);
        }
        return;
    }
    // ---- x prep: h = id & 63, b = id >> 6 ----
    int h = id & 63, b = id >> 6;
    __shared__ float t[32][65];
    __shared__ float sv[32];
    for (int chunk = 0; chunk < 16; chunk++) {
        int ci0 = chunk * 32;
        __syncthreads();
        {
            int r  = tid >> 5;
            int w2 = tid & 31;
#pragma unroll
            for (int rr = 0; rr < 4; rr++) {
                int cl = r * 4 + rr;
                const float* xp = x + (((size_t)b * CIN + ci0 + cl) * HH + h) * WW;
                t[cl][w2]      = xp[w2];
                t[cl][w2 + 32] = xp[w2 + 32];
            }
            if (tid < 32) sv[tid] = g_s[b * CIN + ci0 + tid];
        }
        __syncthreads();
        int ci = tid & 31, wg = tid >> 5;
        float s = sv[ci];
#pragma unroll
        for (int ww = 0; ww < 8; ww++) {
            int w = wg * 8 + ww;
            size_t base = (((size_t)b * 66 + h + 1) * 66 + (w + 1)) * 512 + ci0 + ci;
            g_xcat[base] = to_tf32(t[ci][w] * s);
        }
    }
}

// ---------------------------------------------------------------------------
// Kernel 3: demod[b][co]
// ---------------------------------------------------------------------------
__global__ void k_demod(const float* __restrict__ w) {
    int co = blockIdx.x;
    int t  = threadIdx.x;
    float acc[BB];
#pragma unroll
    for (int b = 0; b < BB; b++) acc[b] = 0.f;

    for (int ci = t; ci < CIN; ci += 256) {
        const float* wp = w + ((size_t)co * CIN + ci) * 9;
        float wsq = 0.f;
#pragma unroll
        for (int i = 0; i < 9; i++) wsq += wp[i] * wp[i];
#pragma unroll
        for (int b = 0; b < BB; b++) {
            float sv = g_s[b * CIN + ci];
            acc[b] += wsq * sv * sv;
        }
    }

    __shared__ float red[BB][257];
#pragma unroll
    for (int b = 0; b < BB; b++) red[b][t] = acc[b];
    __syncthreads();
    for (int off = 128; off > 0; off >>= 1) {
        if (t < off) {
#pragma unroll
            for (int b = 0; b < BB; b++) red[b][t] += red[b][t + off];
        }
        __syncthreads();
    }
    if (t < BB) {
        float v = red[t][0];
        g_demod[t * COUT + co] = rsqrtf(CONV_SCALE * CONV_SCALE * v + EPS);
    }
}

// ---------------------------------------------------------------------------
// Kernel 4: tf32 HMMA conv, occupancy-2 variant.
// Per CTA: 128 threads (4 warps), M=co(128), N=spatial(128 = 2h x 64w).
// Warp tile: 32co x 128sp (both h rows).  Per stage (8 ci):
//   per kx: 6 A ldsm (3ky x 2mt), then per r=0..3 the distinct patch row
//   fragments, shared across (hrow,ky) with hrow+ky==r; 16 B ldsm per kx.
// Smem: A 2 slots x 36864 + B 2 slots x 8448 = 90624B  -> 2 CTAs/SM.
// 2-slot rings, 2 barriers/stage; cross-CTA overlap hides the bubbles.
// ---------------------------------------------------------------------------
#define NSTG    64
#define A_SLOT  36864
#define B_SLOT  8448
#define B_BASE  (2 * A_SLOT)
#define SMEM_SZ (2 * A_SLOT + 2 * B_SLOT)      /* 90624 */

__global__ __launch_bounds__(128) void k_conv_mma(float* __restrict__ out) {
    extern __shared__ char smem[];
    uint32_t sb = smem_u32(smem);

    int tid  = threadIdx.x;
    int lane = tid & 31;
    int warp = tid >> 5;          // 0..3 -> co
    int mBase = warp * 32;

    int H0  = blockIdx.x * 2;     // 2 output h rows per CTA
    int co0 = blockIdx.y * 128;
    int b   = blockIdx.z;

    const char* xb = (const char*)g_xcat;
    const char* wb = (const char*)g_wcat;

    float acc[2][16][4];          // [mt][hrow*8 + cc4*2 + half][frag]
#pragma unroll
    for (int i = 0; i < 2; i++)
#pragma unroll
        for (int j = 0; j < 16; j++)
#pragma unroll
            for (int k = 0; k < 4; k++) acc[i][j][k] = 0.f;

    // ---- stage loader: 8-ci chunk cc = st ----
    auto load_stage = [&](int st) {
        int slot = st & 1;
        uint32_t As = sb + slot * A_SLOT;
        uint32_t Bp = sb + B_BASE + slot * B_SLOT;
        // A: 9 offsets x 128 co rows x 2 chunks of 16B  (2304 -> 18/thread)
#pragma unroll
        for (int i = tid; i < 9 * 128 * 2; i += 128) {
            int o  = i >> 8;
            int rr = (i >> 1) & 127;
            int c  = i & 1;
            size_t off = (((size_t)o * COUT + co0 + rr) * 512 + st * 8 + c * 4) * 4;
            cpa16(As + o * 4096 + (uint32_t)(rr * 32 + (((c ^ ((rr >> 2) & 1)) & 1) << 4)),
                  wb + off);
        }
        // B patch: 4 x 66 positions x 2 chunks (528)
        for (int i = tid; i < 4 * 66 * 2; i += 128) {
            int pi = i >> 1;
            int c  = i & 1;
            int ph = pi / 66, pw = pi - ph * 66;
            size_t off = ((((size_t)b * 66 + H0 + ph) * 66 + pw) * 512 + st * 8 + c * 4) * 4;
            cpa16(Bp + (uint32_t)(pi * 32 + (((c ^ ((pi >> 2) & 1)) & 1) << 4)),
                  xb + off);
        }
        CP_COMMIT();
    };

    load_stage(0);
    load_stage(1);

    // per-lane fragment addressing
    int aR0  = mBase + (lane & 15);
    int acL  = lane >> 4;
    uint32_t aOff = (uint32_t)(((acL ^ ((aR0 >> 2) & 1)) & 1) << 4);  // invariant in mt
    int nLane = (lane & 7) + ((lane >> 4) << 3);
    int cbL   = (lane >> 3) & 1;

    for (int st = 0; st < NSTG; st++) {
        if (st == NSTG - 1) cp_wait<0>(); else cp_wait<1>();
        __syncthreads();

        uint32_t As = sb + (st & 1) * A_SLOT;
        uint32_t Bp = sb + B_BASE + (st & 1) * B_SLOT;

#pragma unroll
        for (int kx = 0; kx < 3; kx++) {
            uint32_t a[3][2][4];
#pragma unroll
            for (int ky = 0; ky < 3; ky++) {
                uint32_t Ao = As + (ky * 3 + kx) * 4096;
#pragma unroll
                for (int mt = 0; mt < 2; mt++)
                    ldsm4(a[ky][mt], Ao + (uint32_t)((aR0 + mt * 16) * 32) + aOff);
            }
            // base addresses for the 4 distinct patch rows at this kx
            uint32_t bAddr[4];
#pragma unroll
            for (int r = 0; r < 4; r++) {
                int q = r * 66 + kx + nLane;
                bAddr[r] = Bp + (uint32_t)(q * 32) +
                           (uint32_t)(((cbL ^ ((q >> 2) & 1)) & 1) << 4);
            }
#pragma unroll
            for (int cc4 = 0; cc4 < 4; cc4++) {
                uint32_t bf[4][4];
#pragma unroll
                for (int r = 0; r < 4; r++)
                    ldsm4(bf[r], bAddr[r] + (uint32_t)(cc4 * 512));
#pragma unroll
                for (int ky = 0; ky < 3; ky++)
#pragma unroll
                    for (int hrow = 0; hrow < 2; hrow++) {
                        const uint32_t* bfr = bf[hrow + ky];
#pragma unroll
                        for (int mt = 0; mt < 2; mt++) {
                            mma1688(acc[mt][hrow * 8 + cc4 * 2 + 0], a[ky][mt], bfr[0], bfr[1]);
                            mma1688(acc[mt][hrow * 8 + cc4 * 2 + 1], a[ky][mt], bfr[2], bfr[3]);
                        }
                    }
            }
        }

        __syncthreads();
        if (st + 2 < NSTG) load_stage(st + 2);
    }

    // ---- epilogue: demod scale + float2 stores ----
#pragma unroll
    for (int mt = 0; mt < 2; mt++) {
#pragma unroll
        for (int rr = 0; rr < 2; rr++) {
            int co = co0 + mBase + mt * 16 + (lane >> 2) + rr * 8;
            float dm = g_demod[b * COUT + co];
            float* op = out + (((size_t)b * COUT + co) << 12);
#pragma unroll
            for (int hrow = 0; hrow < 2; hrow++) {
                int h = H0 + hrow;
#pragma unroll
                for (int j = 0; j < 8; j++) {
                    int n = (j >> 1) * 16 + (j & 1) * 8 + 2 * (lane & 3);
                    float2 v;
                    v.x = acc[mt][hrow * 8 + j][rr * 2 + 0] * dm;
                    v.y = acc[mt][hrow * 8 + j][rr * 2 + 1] * dm;
                    *(float2*)(op + h * 64 + n) = v;
                }
            }
        }
    }
}

// ---------------------------------------------------------------------------
extern "C" void kernel_launch(void* const* d_in, const int* in_sizes, int n_in,
                              void* d_out, int out_size) {
    const float* x      = (const float*)d_in[0];  // [16,512,64,64]
    const float* style  = (const float*)d_in[1];  // [16,512]
    const float* weight = (const float*)d_in[2];  // [1,512,512,3,3]
    const float* mw     = (const float*)d_in[3];  // [512,512]
    const float* mb     = (const float*)d_in[4];  // [512]
    float* out          = (float*)d_out;          // [16,512,64,64]

    k_style<<<BB, SDIM>>>(style, mw, mb);          // launch 1
    k_prep<<<1536, 256>>>(x, weight);              // launch 2 (fused prep)
    k_demod<<<COUT, 256>>>(weight);                // launch 3
    cudaFuncSetAttribute(k_conv_mma, cudaFuncAttributeMaxDynamicSharedMemorySize, SMEM_SZ);
    {
        dim3 g(32 /*h tiles*/, 4 /*co tiles*/, BB);
        k_conv_mma<<<g, 128, SMEM_SZ>>>(out);      // launch 4 -> ncu captures this
    }
}